// round 15
// baseline (speedup 1.0000x reference)
#include <cuda_runtime.h>
#include <cuda_bf16.h>

// Pillar scatter v3: streaming zero + plain-store paint (no atomics on out).
// out[b,f,y,x] = sum_{p: mask[b,p]==1, coord[b,p,1:3]==(y,x)} pillars[b,p,f]
// B=4, P=12000, NF=64, grid 512x512, output 268 MB fp32.
//
//  1) reset: zero 4 MB count grid + counters
//  2) count: bin active pillars into per-cell slot lists; first toucher of a
//            cell appends it to a compact touched-cell list
//  3) zero:  linear grid-stride float4 zero of the full output (proven
//            streaming pattern, ~5.7 TB/s) — NO per-cell branching
//  4) paint: one warp per touched cell; sum its slot list (collisions
//            resolved here), plain coalesced-read / scattered-store of the
//            final 64 feature values. Overflow (>K) handled inline by the
//            owning warp via the ovf side list (statistically never taken).

#define XS 512
#define GRID_CELLS (XS * XS)   // 262144 = 2^18
#define BMAX 4
#define NFC 64
#define K 8
#define OVF_CAP 4096

__device__ __align__(16) int d_count[BMAX * GRID_CELLS];
__device__ int d_slots[BMAX * GRID_CELLS * K];
__device__ int d_touched[BMAX * 12000];
__device__ int d_touched_n;
__device__ int d_ovf_n;
__device__ int d_ovf[OVF_CAP * 2];   // (pillar, cell) pairs

__global__ void reset_kernel(int n_int4) {
    int i = blockIdx.x * blockDim.x + threadIdx.x;
    if (i == 0) { d_touched_n = 0; d_ovf_n = 0; }
    if (i < n_int4)
        reinterpret_cast<int4*>(d_count)[i] = make_int4(0, 0, 0, 0);
}

__global__ void count_kernel(const int* __restrict__ coord,
                             const int* __restrict__ mask,
                             int BP, int P) {
    int i = blockIdx.x * blockDim.x + threadIdx.x;
    if (i >= BP) return;
    if (mask[i] == 0) return;
    int y = coord[i * 3 + 1];
    int x = coord[i * 3 + 2];
    int b = i / P;
    int cell = b * GRID_CELLS + y * XS + x;
    int pos = atomicAdd(&d_count[cell], 1);
    if (pos < K) {
        d_slots[cell * K + pos] = i;              // global pillar index
    } else {
        int o = atomicAdd(&d_ovf_n, 1);
        if (o < OVF_CAP) { d_ovf[o * 2] = i; d_ovf[o * 2 + 1] = cell; }
    }
    if (pos == 0) {
        int t = atomicAdd(&d_touched_n, 1);
        d_touched[t] = cell;
    }
}

// Pure streaming zero: linear float4 grid-stride, no branching.
__global__ void zero_kernel(float4* __restrict__ out, int n4) {
    int i = blockIdx.x * blockDim.x + threadIdx.x;
    int stride = gridDim.x * blockDim.x;
    float4 z = make_float4(0.f, 0.f, 0.f, 0.f);
    for (; i < n4; i += stride)
        out[i] = z;
}

// One warp per touched cell. Reads slot pillar rows coalesced (256 B each),
// writes 64 final feature values with plain scattered STG.32 (no RMW read).
__global__ void paint_kernel(const float* __restrict__ pillars,
                             float* __restrict__ out) {
    int n = d_touched_n;
    int w = (int)((blockIdx.x * (long)blockDim.x + threadIdx.x) >> 5);
    if (w >= n) return;
    int lane = threadIdx.x & 31;

    int cell = d_touched[w];
    int cnt_raw = d_count[cell];
    int cnt = min(cnt_raw, K);

    float v0 = 0.f, v1 = 0.f;
    for (int s = 0; s < cnt; s++) {
        const float* row = pillars + (long)d_slots[cell * K + s] * NFC;
        v0 += row[lane];
        v1 += row[lane + 32];
    }

    if (cnt_raw > K) {                            // ~never; correctness only
        int no = min(d_ovf_n, OVF_CAP);
        for (int o = 0; o < no; o++) {
            if (d_ovf[o * 2 + 1] == cell) {
                const float* row = pillars + (long)d_ovf[o * 2] * NFC;
                v0 += row[lane];
                v1 += row[lane + 32];
            }
        }
    }

    int b  = cell >> 18;                          // / GRID_CELLS
    int yx = cell & (GRID_CELLS - 1);
    float* obase = out + (long)b * NFC * GRID_CELLS + yx;
    obase[(long)lane * GRID_CELLS] = v0;
    obase[(long)(lane + 32) * GRID_CELLS] = v1;
}

extern "C" void kernel_launch(void* const* d_in, const int* in_sizes, int n_in,
                              void* d_out, int out_size) {
    const float* pillars = (const float*)d_in[0];   // [B, P, NF]
    const int*   coord   = (const int*)d_in[1];     // [B, P, 3]
    const int*   mask    = (const int*)d_in[2];     // [B, P]

    int BP = in_sizes[2];                           // B * P = 48000
    int B  = (int)((long)out_size / ((long)NFC * GRID_CELLS));
    int P  = BP / B;
    float* out = (float*)d_out;

    int n_int4 = (B * GRID_CELLS) / 4;
    reset_kernel<<<(n_int4 + 511) / 512, 512>>>(n_int4);

    count_kernel<<<(BP + 255) / 256, 256>>>(coord, mask, BP, P);

    int n4 = out_size / 4;
    zero_kernel<<<2368, 256>>>((float4*)out, n4);

    // Worst case: every active pillar owns a distinct cell -> BP warps.
    int paint_blocks = (BP * 32 + 255) / 256;       // 6000
    paint_kernel<<<paint_blocks, 256>>>(pillars, out);
}

// round 16
// speedup vs baseline: 1.0699x; 1.0699x over previous
#include <cuda_runtime.h>
#include <cuda_bf16.h>

// Pillar scatter v3: streaming zero + plain-store paint (no atomics on out).
// out[b,f,y,x] = sum_{p: mask[b,p]==1, coord[b,p,1:3]==(y,x)} pillars[b,p,f]
// B=4, P=12000, NF=64, grid 512x512, output 268 MB fp32.
//
//  1) reset: zero 4 MB count grid + counters
//  2) count: bin active pillars into per-cell slot lists; first toucher of a
//            cell appends it to a compact touched-cell list
//  3) zero:  linear grid-stride float4 zero of the full output (proven
//            streaming pattern, ~5.7 TB/s) — NO per-cell branching
//  4) paint: one warp per touched cell; sum its slot list (collisions
//            resolved here), plain coalesced-read / scattered-store of the
//            final 64 feature values. Overflow (>K) handled inline by the
//            owning warp via the ovf side list (statistically never taken).

#define XS 512
#define GRID_CELLS (XS * XS)   // 262144 = 2^18
#define BMAX 4
#define NFC 64
#define K 8
#define OVF_CAP 4096

__device__ __align__(16) int d_count[BMAX * GRID_CELLS];
__device__ int d_slots[BMAX * GRID_CELLS * K];
__device__ int d_touched[BMAX * 12000];
__device__ int d_touched_n;
__device__ int d_ovf_n;
__device__ int d_ovf[OVF_CAP * 2];   // (pillar, cell) pairs

__global__ void reset_kernel(int n_int4) {
    int i = blockIdx.x * blockDim.x + threadIdx.x;
    if (i == 0) { d_touched_n = 0; d_ovf_n = 0; }
    if (i < n_int4)
        reinterpret_cast<int4*>(d_count)[i] = make_int4(0, 0, 0, 0);
}

__global__ void count_kernel(const int* __restrict__ coord,
                             const int* __restrict__ mask,
                             int BP, int P) {
    int i = blockIdx.x * blockDim.x + threadIdx.x;
    if (i >= BP) return;
    if (mask[i] == 0) return;
    int y = coord[i * 3 + 1];
    int x = coord[i * 3 + 2];
    int b = i / P;
    int cell = b * GRID_CELLS + y * XS + x;
    int pos = atomicAdd(&d_count[cell], 1);
    if (pos < K) {
        d_slots[cell * K + pos] = i;              // global pillar index
    } else {
        int o = atomicAdd(&d_ovf_n, 1);
        if (o < OVF_CAP) { d_ovf[o * 2] = i; d_ovf[o * 2 + 1] = cell; }
    }
    if (pos == 0) {
        int t = atomicAdd(&d_touched_n, 1);
        d_touched[t] = cell;
    }
}

// Pure streaming zero: linear float4 grid-stride, no branching.
__global__ void zero_kernel(float4* __restrict__ out, int n4) {
    int i = blockIdx.x * blockDim.x + threadIdx.x;
    int stride = gridDim.x * blockDim.x;
    float4 z = make_float4(0.f, 0.f, 0.f, 0.f);
    for (; i < n4; i += stride)
        out[i] = z;
}

// One warp per touched cell. Reads slot pillar rows coalesced (256 B each),
// writes 64 final feature values with plain scattered STG.32 (no RMW read).
__global__ void paint_kernel(const float* __restrict__ pillars,
                             float* __restrict__ out) {
    int n = d_touched_n;
    int w = (int)((blockIdx.x * (long)blockDim.x + threadIdx.x) >> 5);
    if (w >= n) return;
    int lane = threadIdx.x & 31;

    int cell = d_touched[w];
    int cnt_raw = d_count[cell];
    int cnt = min(cnt_raw, K);

    float v0 = 0.f, v1 = 0.f;
    for (int s = 0; s < cnt; s++) {
        const float* row = pillars + (long)d_slots[cell * K + s] * NFC;
        v0 += row[lane];
        v1 += row[lane + 32];
    }

    if (cnt_raw > K) {                            // ~never; correctness only
        int no = min(d_ovf_n, OVF_CAP);
        for (int o = 0; o < no; o++) {
            if (d_ovf[o * 2 + 1] == cell) {
                const float* row = pillars + (long)d_ovf[o * 2] * NFC;
                v0 += row[lane];
                v1 += row[lane + 32];
            }
        }
    }

    int b  = cell >> 18;                          // / GRID_CELLS
    int yx = cell & (GRID_CELLS - 1);
    float* obase = out + (long)b * NFC * GRID_CELLS + yx;
    obase[(long)lane * GRID_CELLS] = v0;
    obase[(long)(lane + 32) * GRID_CELLS] = v1;
}

extern "C" void kernel_launch(void* const* d_in, const int* in_sizes, int n_in,
                              void* d_out, int out_size) {
    const float* pillars = (const float*)d_in[0];   // [B, P, NF]
    const int*   coord   = (const int*)d_in[1];     // [B, P, 3]
    const int*   mask    = (const int*)d_in[2];     // [B, P]

    int BP = in_sizes[2];                           // B * P = 48000
    int B  = (int)((long)out_size / ((long)NFC * GRID_CELLS));
    int P  = BP / B;
    float* out = (float*)d_out;

    int n_int4 = (B * GRID_CELLS) / 4;
    reset_kernel<<<(n_int4 + 511) / 512, 512>>>(n_int4);

    count_kernel<<<(BP + 255) / 256, 256>>>(coord, mask, BP, P);

    int n4 = out_size / 4;
    zero_kernel<<<2368, 256>>>((float4*)out, n4);

    // Worst case: every active pillar owns a distinct cell -> BP warps.
    int paint_blocks = (BP * 32 + 255) / 256;       // 6000
    paint_kernel<<<paint_blocks, 256>>>(pillars, out);
}